// round 1
// baseline (speedup 1.0000x reference)
#include <cuda_runtime.h>
#include <cuda_bf16.h>

#define Bb 8
#define Nn 4096
#define ATTR 16
#define Hh 64
#define STEPS 8
#define CAP 128
#define ROWS (Bb*Nn)            // 32768

typedef unsigned long long ull;

// ------------------------- device scratch -------------------------
__device__ float g_h[ROWS*Hh];       // 8 MB
__device__ float g_ain[ROWS*Hh];     // 8 MB
__device__ float g_aout[ROWS*Hh];    // 8 MB
__device__ int   g_incnt[ROWS];
__device__ int   g_outcnt[ROWS];
__device__ int   g_incol[(size_t)ROWS*CAP];   // 16.8 MB
__device__ int   g_outcol[(size_t)ROWS*CAP];  // 16.8 MB

// ------------------------- f32x2 helpers -------------------------
__device__ __forceinline__ void fma2(ull &acc, ull a, ull b) {
    asm("fma.rn.f32x2 %0, %1, %2, %0;" : "+l"(acc) : "l"(a), "l"(b));
}
__device__ __forceinline__ ull pack2(float w) {
    ull r; asm("mov.b64 %0, {%1, %1};" : "=l"(r) : "f"(w)); return r;
}
__device__ __forceinline__ float2 unpack2(ull v) {
    float2 f; asm("mov.b64 {%0, %1}, %2;" : "=f"(f.x), "=f"(f.y) : "l"(v)); return f;
}
__device__ __forceinline__ float sigmoidf_(float x) {
    return 1.f / (1.f + __expf(-x));
}
__device__ __forceinline__ float tanhf_(float x) {
    float e = __expf(2.f * x);          // inf -> 1, 0 -> -1, no NaN
    return 1.f - 2.f / (e + 1.f);
}

// ------------------------- kernels -------------------------
__global__ void zero_counts() {
    int i = blockIdx.x * blockDim.x + threadIdx.x;
    if (i < ROWS) { g_incnt[i] = 0; g_outcnt[i] = 0; }
}

// one block per (b,i) row; scan 4096 floats as float4, append edges
__global__ void build_csr(const float* __restrict__ adj) {
    int row = blockIdx.x;              // b*N + i
    int b   = row >> 12;
    int i   = row & (Nn - 1);
    const float4* a4 = reinterpret_cast<const float4*>(adj + (size_t)row * Nn);
    for (int t = threadIdx.x; t < Nn / 4; t += blockDim.x) {
        float4 v = a4[t];
        int j = 4 * t;
        #pragma unroll
        for (int u = 0; u < 4; u++) {
            float val = (u == 0) ? v.x : (u == 1) ? v.y : (u == 2) ? v.z : v.w;
            if (val != 0.f) {
                int jc = j + u;
                int p = atomicAdd(&g_incnt[row], 1);
                if (p < CAP) g_incol[(size_t)row * CAP + p] = jc;
                int q = atomicAdd(&g_outcnt[(b << 12) + jc], 1);
                if (q < CAP) g_outcol[((size_t)((b << 12) + jc)) * CAP + q] = i;
            }
        }
    }
}

// h0 = relu(attr @ Wi.T + bi); block = 4 rows x 64 cols
__global__ void init_h(const float* __restrict__ attr,
                       const float* __restrict__ Wi,
                       const float* __restrict__ bi) {
    __shared__ float sWiT[ATTR * Hh];   // [a][col]
    __shared__ float sAttr[4][ATTR];
    int col = threadIdx.x & 63;
    int r   = threadIdx.x >> 6;
    int row = blockIdx.x * 4 + r;
    for (int t = threadIdx.x; t < ATTR * Hh; t += 256) {
        int a = t >> 6, c = t & 63;
        sWiT[t] = Wi[c * ATTR + a];
    }
    if (col < ATTR) sAttr[r][col] = attr[(size_t)row * ATTR + col];
    __syncthreads();
    float acc = bi[col];
    #pragma unroll
    for (int a = 0; a < ATTR; a++) acc = fmaf(sAttr[r][a], sWiT[a * 64 + col], acc);
    g_h[(size_t)row * Hh + col] = fmaxf(acc, 0.f);
}

// one block per row; warps 0-1 -> a_in, warps 2-3 -> a_out
__global__ void spmm() {
    int row = blockIdx.x;
    int dir = threadIdx.x >> 6;
    int col = threadIdx.x & 63;
    int b   = row >> 12;
    const float* __restrict__ hb = g_h + ((size_t)(b << 12)) * Hh;
    const int* __restrict__ cl = (dir ? g_outcol : g_incol) + (size_t)row * CAP;
    int cnt = dir ? g_outcnt[row] : g_incnt[row];
    cnt = min(cnt, CAP);
    float acc = 0.f;
    int t = 0;
    for (; t + 8 <= cnt; t += 8) {
        int j[8];
        #pragma unroll
        for (int u = 0; u < 8; u++) j[u] = cl[t + u];
        float v[8];
        #pragma unroll
        for (int u = 0; u < 8; u++) v[u] = hb[(size_t)j[u] * Hh + col];
        #pragma unroll
        for (int u = 0; u < 8; u++) acc += v[u];
    }
    for (; t < cnt; t++) acc += hb[(size_t)cl[t] * Hh + col];
    float* dst = dir ? g_aout : g_ain;
    dst[(size_t)row * Hh + col] = acc;
}

// fused GRU update, persistent grid, f32x2 math.
// smem: sW4[192*64] float4 {wz,wr,wh,0} transposed [k][col]; XS[8][192][4]
#define GRU_THREADS 512
#define GRU_SMEM (192*64*16 + 8*192*4*4)   // 196608 + 24576 = 221184
__global__ void __launch_bounds__(GRU_THREADS, 1)
gru_step(const float* __restrict__ Wz, const float* __restrict__ bz,
         const float* __restrict__ Wr, const float* __restrict__ br,
         const float* __restrict__ Wh, const float* __restrict__ bh) {
    extern __shared__ float4 smem4[];
    float4* sW = smem4;                         // 12288 float4
    float*  XS = reinterpret_cast<float*>(smem4 + 192 * 64);

    int tid = threadIdx.x;
    int col = tid & 63;
    int g   = tid >> 6;      // 0..7
    // transposed weight load: sW[k*64+col] = {Wz[col][k], Wr[col][k], Wh[col][k], 0}
    for (int idx = tid; idx < 192 * 64; idx += GRU_THREADS) {
        int c = idx & 63, k = idx >> 6;
        sW[idx] = make_float4(Wz[c * 192 + k], Wr[c * 192 + k], Wh[c * 192 + k], 0.f);
    }
    float bzc = bz[col], brc = br[col], bhc = bh[col];
    __syncthreads();

    float* xsg = XS + g * (192 * 4);

    for (int base = blockIdx.x * 32; base < ROWS; base += gridDim.x * 32) {
        int row0 = base + g * 4;
        float hv[4];
        // stage xs transposed: [k][r]
        #pragma unroll
        for (int r = 0; r < 4; r++) {
            size_t off = (size_t)(row0 + r) * Hh + col;
            float ai = g_ain[off];
            float ao = g_aout[off];
            float hh = g_h[off];
            hv[r] = hh;
            xsg[(col)       * 4 + r] = ai;
            xsg[(64 + col)  * 4 + r] = ao;
            xsg[(128 + col) * 4 + r] = hh;
        }
        __syncthreads();

        ull az01 = pack2(bzc), az23 = pack2(bzc);
        ull ar01 = pack2(brc), ar23 = pack2(brc);
        ull ah01 = pack2(bhc), ah23 = pack2(bhc);

        #pragma unroll 4
        for (int k = 0; k < 128; k++) {
            float4 w = sW[k * 64 + col];
            ull wz2 = pack2(w.x), wr2 = pack2(w.y), wh2 = pack2(w.z);
            ull x01 = *reinterpret_cast<const ull*>(xsg + k * 4);
            ull x23 = *reinterpret_cast<const ull*>(xsg + k * 4 + 2);
            fma2(az01, wz2, x01); fma2(az23, wz2, x23);
            fma2(ar01, wr2, x01); fma2(ar23, wr2, x23);
            fma2(ah01, wh2, x01); fma2(ah23, wh2, x23);
        }
        #pragma unroll 4
        for (int k = 128; k < 192; k++) {
            float4 w = sW[k * 64 + col];
            ull wz2 = pack2(w.x), wr2 = pack2(w.y);
            ull x01 = *reinterpret_cast<const ull*>(xsg + k * 4);
            ull x23 = *reinterpret_cast<const ull*>(xsg + k * 4 + 2);
            fma2(az01, wz2, x01); fma2(az23, wz2, x23);
            fma2(ar01, wr2, x01); fma2(ar23, wr2, x23);
        }

        float2 z01 = unpack2(az01), z23 = unpack2(az23);
        float2 r01 = unpack2(ar01), r23 = unpack2(ar23);
        float zf[4] = { sigmoidf_(z01.x), sigmoidf_(z01.y), sigmoidf_(z23.x), sigmoidf_(z23.y) };
        float rf[4] = { sigmoidf_(r01.x), sigmoidf_(r01.y), sigmoidf_(r23.x), sigmoidf_(r23.y) };

        // overwrite h slots with r*h
        #pragma unroll
        for (int r = 0; r < 4; r++) xsg[(128 + col) * 4 + r] = rf[r] * hv[r];
        __syncthreads();

        #pragma unroll 4
        for (int k = 128; k < 192; k++) {
            float4 w = sW[k * 64 + col];
            ull wh2 = pack2(w.z);
            ull x01 = *reinterpret_cast<const ull*>(xsg + k * 4);
            ull x23 = *reinterpret_cast<const ull*>(xsg + k * 4 + 2);
            fma2(ah01, wh2, x01); fma2(ah23, wh2, x23);
        }
        float2 h01 = unpack2(ah01), h23 = unpack2(ah23);
        float hnf[4] = { tanhf_(h01.x), tanhf_(h01.y), tanhf_(h23.x), tanhf_(h23.y) };
        #pragma unroll
        for (int r = 0; r < 4; r++) {
            float hnew = hv[r] + zf[r] * (hnf[r] - hv[r]);
            g_h[(size_t)(row0 + r) * Hh + col] = hnew;
        }
        __syncthreads();   // protect XS before next tile's staging
    }
}

// out[row] = dot(h[row], Wo) + bo   (warp per row)
__global__ void out_k(const float* __restrict__ Wo, const float* __restrict__ bo,
                      float* __restrict__ out) {
    int row  = blockIdx.x * 8 + (threadIdx.x >> 5);
    int lane = threadIdx.x & 31;
    const float* hr = g_h + (size_t)row * Hh;
    float a = hr[lane] * Wo[lane] + hr[lane + 32] * Wo[lane + 32];
    #pragma unroll
    for (int o = 16; o; o >>= 1) a += __shfl_xor_sync(0xffffffffu, a, o);
    if (lane == 0) out[row] = a + bo[0];
}

// ------------------------- launch -------------------------
extern "C" void kernel_launch(void* const* d_in, const int* in_sizes, int n_in,
                              void* d_out, int out_size) {
    const float* attr = (const float*)d_in[0];
    const float* adj  = (const float*)d_in[1];
    const float* Wi   = (const float*)d_in[2];
    const float* bi   = (const float*)d_in[3];
    const float* Wz   = (const float*)d_in[4];
    const float* bz   = (const float*)d_in[5];
    const float* Wr   = (const float*)d_in[6];
    const float* br   = (const float*)d_in[7];
    const float* Wh   = (const float*)d_in[8];
    const float* bh   = (const float*)d_in[9];
    const float* Wo   = (const float*)d_in[10];
    const float* bo   = (const float*)d_in[11];
    float* out = (float*)d_out;

    static bool attr_set = false;
    if (!attr_set) {
        cudaFuncSetAttribute(gru_step, cudaFuncAttributeMaxDynamicSharedMemorySize, GRU_SMEM);
        attr_set = true;
    }

    zero_counts<<<(ROWS + 255) / 256, 256>>>();
    build_csr<<<ROWS, 256>>>(adj);
    init_h<<<ROWS / 4, 256>>>(attr, Wi, bi);
    for (int s = 0; s < STEPS; s++) {
        spmm<<<ROWS, 128>>>();
        gru_step<<<152, GRU_THREADS, GRU_SMEM>>>(Wz, bz, Wr, br, Wh, bh);
    }
    out_k<<<ROWS / 8, 256>>>(Wo, bo, out);
}

// round 2
// speedup vs baseline: 1.2043x; 1.2043x over previous
#include <cuda_runtime.h>
#include <cuda_bf16.h>

#define Bb 8
#define Nn 4096
#define ATTR 16
#define Hh 64
#define STEPS 8
#define CAP 128
#define ROWS (Bb*Nn)            // 32768

typedef unsigned long long ull;

// ------------------------- device scratch -------------------------
__device__ float g_h[ROWS*Hh];       // 8 MB
__device__ float g_ain[ROWS*Hh];     // 8 MB
__device__ float g_aout[ROWS*Hh];    // 8 MB
__device__ int   g_incnt[ROWS];
__device__ int   g_outcnt[ROWS];
__device__ int   g_incol[(size_t)ROWS*CAP];   // 16.8 MB
__device__ int   g_outcol[(size_t)ROWS*CAP];  // 16.8 MB

// ------------------------- f32x2 helpers -------------------------
__device__ __forceinline__ void fma2(ull &acc, ull a, ull b) {
    asm("fma.rn.f32x2 %0, %1, %2, %0;" : "+l"(acc) : "l"(a), "l"(b));
}
__device__ __forceinline__ void add2(ull &acc, ull v) {
    asm("add.rn.f32x2 %0, %0, %1;" : "+l"(acc) : "l"(v));
}
__device__ __forceinline__ ull pack2(float w) {
    ull r; asm("mov.b64 %0, {%1, %1};" : "=l"(r) : "f"(w)); return r;
}
__device__ __forceinline__ ull packf2(float a, float b) {
    ull r; asm("mov.b64 %0, {%1, %2};" : "=l"(r) : "f"(a), "f"(b)); return r;
}
__device__ __forceinline__ float2 unpack2(ull v) {
    float2 f; asm("mov.b64 {%0, %1}, %2;" : "=f"(f.x), "=f"(f.y) : "l"(v)); return f;
}
__device__ __forceinline__ float sigmoidf_(float x) {
    return 1.f / (1.f + __expf(-x));
}
__device__ __forceinline__ float tanhf_(float x) {
    float e = __expf(2.f * x);          // inf -> 1, 0 -> -1, no NaN
    return 1.f - 2.f / (e + 1.f);
}

// ------------------------- small kernels -------------------------
__global__ void zero_counts() {
    int i = blockIdx.x * blockDim.x + threadIdx.x;
    if (i < ROWS) { g_incnt[i] = 0; g_outcnt[i] = 0; }
}

__global__ void build_csr(const float* __restrict__ adj) {
    int row = blockIdx.x;              // b*N + i
    int b   = row >> 12;
    int i   = row & (Nn - 1);
    const float4* a4 = reinterpret_cast<const float4*>(adj + (size_t)row * Nn);
    for (int t = threadIdx.x; t < Nn / 4; t += blockDim.x) {
        float4 v = a4[t];
        int j = 4 * t;
        #pragma unroll
        for (int u = 0; u < 4; u++) {
            float val = (u == 0) ? v.x : (u == 1) ? v.y : (u == 2) ? v.z : v.w;
            if (val != 0.f) {
                int jc = j + u;
                int p = atomicAdd(&g_incnt[row], 1);
                if (p < CAP) g_incol[(size_t)row * CAP + p] = jc;
                int q = atomicAdd(&g_outcnt[(b << 12) + jc], 1);
                if (q < CAP) g_outcol[((size_t)((b << 12) + jc)) * CAP + q] = i;
            }
        }
    }
}

__global__ void init_h(const float* __restrict__ attr,
                       const float* __restrict__ Wi,
                       const float* __restrict__ bi) {
    __shared__ float sWiT[ATTR * Hh];   // [a][col]
    __shared__ float sAttr[4][ATTR];
    int col = threadIdx.x & 63;
    int r   = threadIdx.x >> 6;
    int row = blockIdx.x * 4 + r;
    for (int t = threadIdx.x; t < ATTR * Hh; t += 256) {
        int a = t >> 6, c = t & 63;
        sWiT[t] = Wi[c * ATTR + a];
    }
    if (col < ATTR) sAttr[r][col] = attr[(size_t)row * ATTR + col];
    __syncthreads();
    float acc = bi[col];
    #pragma unroll
    for (int a = 0; a < ATTR; a++) acc = fmaf(sAttr[r][a], sWiT[a * 64 + col], acc);
    g_h[(size_t)row * Hh + col] = fmaxf(acc, 0.f);
}

// ------------------------- spmm v2: warp per (row, dir), float2 -------------------------
__global__ void __launch_bounds__(256) spmm2() {
    int w    = threadIdx.x >> 5;          // 0..7
    int lane = threadIdx.x & 31;
    int row  = blockIdx.x * 4 + (w >> 1);
    int dir  = w & 1;
    int b    = row >> 12;
    const ull* __restrict__ hb = reinterpret_cast<const ull*>(g_h + ((size_t)(b << 12)) * Hh);
    const int* __restrict__ cl = (dir ? g_outcol : g_incol) + (size_t)row * CAP;
    int cnt = dir ? g_outcnt[row] : g_incnt[row];
    cnt = min(cnt, CAP);
    ull acc = 0;   // two packed zeros (0x0 bits == 0.0f)
    int t = 0;
    for (; t + 8 <= cnt; t += 8) {
        int j[8];
        #pragma unroll
        for (int u = 0; u < 8; u++) j[u] = __ldg(cl + t + u);
        ull v[8];
        #pragma unroll
        for (int u = 0; u < 8; u++) v[u] = hb[(size_t)j[u] * 32 + lane];
        #pragma unroll
        for (int u = 0; u < 8; u++) add2(acc, v[u]);
    }
    for (; t < cnt; t++) add2(acc, hb[(size_t)cl[t] * 32 + lane]);
    float* dst = (dir ? g_aout : g_ain) + (size_t)row * Hh;
    *reinterpret_cast<ull*>(dst + 2 * lane) = acc;
}

// ------------------------- gru v2: register-tiled GEMM -------------------------
// CTA: 64 rows x 192 cols, 256 threads; thread tile = 8 rows x 6 cols (f32x2 pairs).
// smem: sW[192][192] (Wh cols zeroed for k>=128) + sWh2[64][64] + sX[192][68 padded]
#define XPITCH 68
#define SW_FLOATS (192*192)
#define SWH2_OFF  SW_FLOATS
#define SX_OFF    (SW_FLOATS + 64*64)
#define GRU2_SMEM ((SX_OFF + 192*XPITCH) * 4)   // 216,064 bytes
#define NTILES (ROWS/64)                         // 512

__global__ void __launch_bounds__(256, 1)
gru2(const float* __restrict__ Wz, const float* __restrict__ bz,
     const float* __restrict__ Wr, const float* __restrict__ br,
     const float* __restrict__ Wh, const float* __restrict__ bh) {
    extern __shared__ float sm[];
    float* sW   = sm;               // [k*192 + c]
    float* sWh2 = sm + SWH2_OFF;    // [k*64 + c], Wh[:,128+k]
    float* sX   = sm + SX_OFF;      // [k*XPITCH + r]

    int tid = threadIdx.x;
    int tc  = tid & 31;             // thread col 0..31
    int tr  = tid >> 5;             // thread row-group 0..7 (8 rows each)

    // stage packed/transposed weights once
    for (int idx = tid; idx < SW_FLOATS; idx += 256) {
        int k = idx / 192, c = idx - k * 192;
        float v;
        if (c < 64)       v = Wz[c * 192 + k];
        else if (c < 128) v = Wr[(c - 64) * 192 + k];
        else              v = (k < 128) ? Wh[(c - 128) * 192 + k] : 0.f;
        sW[idx] = v;
    }
    for (int idx = tid; idx < 64 * 64; idx += 256) {
        int k = idx >> 6, c = idx & 63;
        sWh2[idx] = Wh[c * 192 + 128 + k];
    }
    float bz0 = bz[tc], bz1 = bz[tc + 32];
    float br0 = br[tc], br1 = br[tc + 32];
    float bh0 = bh[tc], bh1 = bh[tc + 32];
    __syncthreads();

    for (int tile = blockIdx.x; tile < NTILES; tile += gridDim.x) {
        int base = tile * 64;
        // ---- stage sX transposed: sX[k][r] ----
        {
            int col = tid & 63, rr = tid >> 6;      // 4 rows per pass
            for (int r = rr; r < 64; r += 4) {
                size_t off = (size_t)(base + r) * Hh + col;
                sX[col * XPITCH + r]          = g_ain[off];
                sX[(64 + col) * XPITCH + r]   = g_aout[off];
                sX[(128 + col) * XPITCH + r]  = g_h[off];
            }
        }
        __syncthreads();

        ull acc[6][4];
        #pragma unroll
        for (int p = 0; p < 4; p++) {
            acc[0][p] = pack2(bz0); acc[1][p] = pack2(bz1);
            acc[2][p] = pack2(br0); acc[3][p] = pack2(br1);
            acc[4][p] = pack2(bh0); acc[5][p] = pack2(bh1);
        }
        const float* xp = sX + tr * 8;

        // ---- phase A: k < 128 -> all 6 output cols ----
        #pragma unroll 2
        for (int k = 0; k < 128; k++) {
            float4 xa = *reinterpret_cast<const float4*>(xp + k * XPITCH);
            float4 xb = *reinterpret_cast<const float4*>(xp + k * XPITCH + 4);
            ull x0 = packf2(xa.x, xa.y), x1 = packf2(xa.z, xa.w);
            ull x2 = packf2(xb.x, xb.y), x3 = packf2(xb.z, xb.w);
            const float* wp = sW + k * 192 + tc;
            #pragma unroll
            for (int jj = 0; jj < 6; jj++) {
                ull w2 = pack2(wp[32 * jj]);
                fma2(acc[jj][0], w2, x0); fma2(acc[jj][1], w2, x1);
                fma2(acc[jj][2], w2, x2); fma2(acc[jj][3], w2, x3);
            }
        }
        // ---- phase A tail: k in [128,192) -> z,r only ----
        #pragma unroll 2
        for (int k = 128; k < 192; k++) {
            float4 xa = *reinterpret_cast<const float4*>(xp + k * XPITCH);
            float4 xb = *reinterpret_cast<const float4*>(xp + k * XPITCH + 4);
            ull x0 = packf2(xa.x, xa.y), x1 = packf2(xa.z, xa.w);
            ull x2 = packf2(xb.x, xb.y), x3 = packf2(xb.z, xb.w);
            const float* wp = sW + k * 192 + tc;
            #pragma unroll
            for (int jj = 0; jj < 4; jj++) {
                ull w2 = pack2(wp[32 * jj]);
                fma2(acc[jj][0], w2, x0); fma2(acc[jj][1], w2, x1);
                fma2(acc[jj][2], w2, x2); fma2(acc[jj][3], w2, x3);
            }
        }

        // ---- gates ----
        float z0[8], z1[8], r0[8], r1[8], h0[8], h1[8];
        #pragma unroll
        for (int p = 0; p < 4; p++) {
            float2 a0 = unpack2(acc[0][p]); z0[2*p] = sigmoidf_(a0.x); z0[2*p+1] = sigmoidf_(a0.y);
            float2 a1 = unpack2(acc[1][p]); z1[2*p] = sigmoidf_(a1.x); z1[2*p+1] = sigmoidf_(a1.y);
            float2 a2 = unpack2(acc[2][p]); r0[2*p] = sigmoidf_(a2.x); r0[2*p+1] = sigmoidf_(a2.y);
            float2 a3 = unpack2(acc[3][p]); r1[2*p] = sigmoidf_(a3.x); r1[2*p+1] = sigmoidf_(a3.y);
        }
        // h_old from sX (region k>=128, untouched by rh writes)
        {
            float4 ha = *reinterpret_cast<const float4*>(sX + (128 + tc) * XPITCH + tr * 8);
            float4 hb4 = *reinterpret_cast<const float4*>(sX + (128 + tc) * XPITCH + tr * 8 + 4);
            h0[0]=ha.x; h0[1]=ha.y; h0[2]=ha.z; h0[3]=ha.w;
            h0[4]=hb4.x; h0[5]=hb4.y; h0[6]=hb4.z; h0[7]=hb4.w;
            float4 hc = *reinterpret_cast<const float4*>(sX + (160 + tc) * XPITCH + tr * 8);
            float4 hd = *reinterpret_cast<const float4*>(sX + (160 + tc) * XPITCH + tr * 8 + 4);
            h1[0]=hc.x; h1[1]=hc.y; h1[2]=hc.z; h1[3]=hc.w;
            h1[4]=hd.x; h1[5]=hd.y; h1[6]=hd.z; h1[7]=hd.w;
        }
        __syncthreads();   // phase A reads of sX[k<64] done before rh overwrite

        // rh into sX rows k=0..63 (rh[c][r] = r*h)
        {
            float4 wa = make_float4(r0[0]*h0[0], r0[1]*h0[1], r0[2]*h0[2], r0[3]*h0[3]);
            float4 wb = make_float4(r0[4]*h0[4], r0[5]*h0[5], r0[6]*h0[6], r0[7]*h0[7]);
            *reinterpret_cast<float4*>(sX + tc * XPITCH + tr * 8)     = wa;
            *reinterpret_cast<float4*>(sX + tc * XPITCH + tr * 8 + 4) = wb;
            float4 wc = make_float4(r1[0]*h1[0], r1[1]*h1[1], r1[2]*h1[2], r1[3]*h1[3]);
            float4 wd = make_float4(r1[4]*h1[4], r1[5]*h1[5], r1[6]*h1[6], r1[7]*h1[7]);
            *reinterpret_cast<float4*>(sX + (tc + 32) * XPITCH + tr * 8)     = wc;
            *reinterpret_cast<float4*>(sX + (tc + 32) * XPITCH + tr * 8 + 4) = wd;
        }
        __syncthreads();

        // ---- phase B: hn_rest over rh, k=0..63 ----
        #pragma unroll 2
        for (int k = 0; k < 64; k++) {
            float4 xa = *reinterpret_cast<const float4*>(xp + k * XPITCH);
            float4 xb = *reinterpret_cast<const float4*>(xp + k * XPITCH + 4);
            ull x0 = packf2(xa.x, xa.y), x1 = packf2(xa.z, xa.w);
            ull x2 = packf2(xb.x, xb.y), x3 = packf2(xb.z, xb.w);
            ull w4 = pack2(sWh2[k * 64 + tc]);
            ull w5 = pack2(sWh2[k * 64 + tc + 32]);
            fma2(acc[4][0], w4, x0); fma2(acc[4][1], w4, x1);
            fma2(acc[4][2], w4, x2); fma2(acc[4][3], w4, x3);
            fma2(acc[5][0], w5, x0); fma2(acc[5][1], w5, x1);
            fma2(acc[5][2], w5, x2); fma2(acc[5][3], w5, x3);
        }

        // ---- update + store ----
        #pragma unroll
        for (int p = 0; p < 4; p++) {
            float2 a4 = unpack2(acc[4][p]);
            float2 a5 = unpack2(acc[5][p]);
            float hn;
            int i0 = 2 * p, i1 = 2 * p + 1;
            int row0 = base + tr * 8;
            hn = tanhf_(a4.x);
            g_h[(size_t)(row0 + i0) * Hh + tc]      = h0[i0] + z0[i0] * (hn - h0[i0]);
            hn = tanhf_(a4.y);
            g_h[(size_t)(row0 + i1) * Hh + tc]      = h0[i1] + z0[i1] * (hn - h0[i1]);
            hn = tanhf_(a5.x);
            g_h[(size_t)(row0 + i0) * Hh + tc + 32] = h1[i0] + z1[i0] * (hn - h1[i0]);
            hn = tanhf_(a5.y);
            g_h[(size_t)(row0 + i1) * Hh + tc + 32] = h1[i1] + z1[i1] * (hn - h1[i1]);
        }
        __syncthreads();   // protect sX before next tile staging
    }
}

// out[row] = dot(h[row], Wo) + bo   (warp per row)
__global__ void out_k(const float* __restrict__ Wo, const float* __restrict__ bo,
                      float* __restrict__ out) {
    int row  = blockIdx.x * 8 + (threadIdx.x >> 5);
    int lane = threadIdx.x & 31;
    const float* hr = g_h + (size_t)row * Hh;
    float a = hr[lane] * Wo[lane] + hr[lane + 32] * Wo[lane + 32];
    #pragma unroll
    for (int o = 16; o; o >>= 1) a += __shfl_xor_sync(0xffffffffu, a, o);
    if (lane == 0) out[row] = a + bo[0];
}

// ------------------------- launch -------------------------
extern "C" void kernel_launch(void* const* d_in, const int* in_sizes, int n_in,
                              void* d_out, int out_size) {
    const float* attr = (const float*)d_in[0];
    const float* adj  = (const float*)d_in[1];
    const float* Wi   = (const float*)d_in[2];
    const float* bi   = (const float*)d_in[3];
    const float* Wz   = (const float*)d_in[4];
    const float* bz   = (const float*)d_in[5];
    const float* Wr   = (const float*)d_in[6];
    const float* br   = (const float*)d_in[7];
    const float* Wh   = (const float*)d_in[8];
    const float* bh   = (const float*)d_in[9];
    const float* Wo   = (const float*)d_in[10];
    const float* bo   = (const float*)d_in[11];
    float* out = (float*)d_out;

    static bool attr_set = false;
    if (!attr_set) {
        cudaFuncSetAttribute(gru2, cudaFuncAttributeMaxDynamicSharedMemorySize, GRU2_SMEM);
        attr_set = true;
    }

    zero_counts<<<(ROWS + 255) / 256, 256>>>();
    build_csr<<<ROWS, 256>>>(adj);
    init_h<<<ROWS / 4, 256>>>(attr, Wi, bi);
    for (int s = 0; s < STEPS; s++) {
        spmm2<<<ROWS / 4, 256>>>();
        gru2<<<148, 256, GRU2_SMEM>>>(Wz, bz, Wr, br, Wh, bh);
    }
    out_k<<<ROWS / 8, 256>>>(Wo, bo, out);
}

// round 4
// speedup vs baseline: 1.3236x; 1.0991x over previous
#include <cuda_runtime.h>
#include <cuda_bf16.h>
#include <cstdint>

#define Bb 8
#define Nn 4096
#define ATTR 16
#define Hh 64
#define STEPS 8
#define CAP 128
#define ROWS (Bb*Nn)            // 32768

typedef unsigned long long ull;

// ------------------------- device scratch -------------------------
__device__ float g_h[ROWS*Hh];       // 8 MB
__device__ float g_ain[ROWS*Hh];     // 8 MB
__device__ float g_aout[ROWS*Hh];    // 8 MB
__device__ int   g_incnt[ROWS];
__device__ int   g_outcnt[ROWS];
__device__ int   g_incol[(size_t)ROWS*CAP];   // 16.8 MB
__device__ int   g_outcol[(size_t)ROWS*CAP];  // 16.8 MB
__device__ int   g_sink;

// ------------------------- helpers -------------------------
__device__ __forceinline__ float sigmoidf_(float x) { return 1.f / (1.f + __expf(-x)); }
__device__ __forceinline__ float tanhf_(float x) {
    float e = __expf(2.f * x); return 1.f - 2.f / (e + 1.f);
}
__device__ __forceinline__ uint32_t tf32hi(float x) {
    uint32_t u; asm("cvt.rna.tf32.f32 %0, %1;" : "=r"(u) : "f"(x));
    return u;
}
// hi = tf32(x); lo = x - hi (HW truncates extra mantissa bits of lo)
__device__ __forceinline__ void split2(float x, uint32_t &hi, uint32_t &lo) {
    hi = tf32hi(x);
    lo = __float_as_uint(x - __uint_as_float(hi));
}
__device__ __forceinline__ void mma8(float* d, uint32_t a0, uint32_t a1, uint32_t a2, uint32_t a3,
                                     uint32_t b0, uint32_t b1) {
    asm volatile(
        "mma.sync.aligned.m16n8k8.row.col.f32.tf32.tf32.f32 "
        "{%0,%1,%2,%3}, {%4,%5,%6,%7}, {%8,%9}, {%0,%1,%2,%3};"
        : "+f"(d[0]), "+f"(d[1]), "+f"(d[2]), "+f"(d[3])
        : "r"(a0), "r"(a1), "r"(a2), "r"(a3), "r"(b0), "r"(b1));
}
__device__ __forceinline__ void add2(ull &acc, ull v) {
    asm("add.rn.f32x2 %0, %0, %1;" : "+l"(acc) : "l"(v));
}

// ------------------------- small kernels -------------------------
__global__ void zero_counts() {
    int i = blockIdx.x * blockDim.x + threadIdx.x;
    if (i < ROWS) { g_incnt[i] = 0; g_outcnt[i] = 0; }
}

__global__ void probe() { if (threadIdx.x == 0) g_sink = g_incnt[0] & 0; }

__global__ void build_csr(const float* __restrict__ adj) {
    int row = blockIdx.x;
    int b   = row >> 12;
    int i   = row & (Nn - 1);
    const float4* a4 = reinterpret_cast<const float4*>(adj + (size_t)row * Nn);
    for (int t = threadIdx.x; t < Nn / 4; t += blockDim.x) {
        float4 v = a4[t];
        int j = 4 * t;
        #pragma unroll
        for (int u = 0; u < 4; u++) {
            float val = (u == 0) ? v.x : (u == 1) ? v.y : (u == 2) ? v.z : v.w;
            if (val != 0.f) {
                int jc = j + u;
                int p = atomicAdd(&g_incnt[row], 1);
                if (p < CAP) g_incol[(size_t)row * CAP + p] = jc;
                int q = atomicAdd(&g_outcnt[(b << 12) + jc], 1);
                if (q < CAP) g_outcol[((size_t)((b << 12) + jc)) * CAP + q] = i;
            }
        }
    }
}

__global__ void init_h(const float* __restrict__ attr,
                       const float* __restrict__ Wi,
                       const float* __restrict__ bi) {
    __shared__ float sWiT[ATTR * Hh];
    __shared__ float sAttr[4][ATTR];
    int col = threadIdx.x & 63;
    int r   = threadIdx.x >> 6;
    int row = blockIdx.x * 4 + r;
    for (int t = threadIdx.x; t < ATTR * Hh; t += 256) {
        int a = t >> 6, c = t & 63;
        sWiT[t] = Wi[c * ATTR + a];
    }
    if (col < ATTR) sAttr[r][col] = attr[(size_t)row * ATTR + col];
    __syncthreads();
    float acc = bi[col];
    #pragma unroll
    for (int a = 0; a < ATTR; a++) acc = fmaf(sAttr[r][a], sWiT[a * 64 + col], acc);
    g_h[(size_t)row * Hh + col] = fmaxf(acc, 0.f);
}

// ------------------------- spmm (unchanged from R2) -------------------------
__global__ void __launch_bounds__(256) spmm2() {
    int w    = threadIdx.x >> 5;
    int lane = threadIdx.x & 31;
    int row  = blockIdx.x * 4 + (w >> 1);
    int dir  = w & 1;
    int b    = row >> 12;
    const ull* __restrict__ hb = reinterpret_cast<const ull*>(g_h + ((size_t)(b << 12)) * Hh);
    const int* __restrict__ cl = (dir ? g_outcol : g_incol) + (size_t)row * CAP;
    int cnt = dir ? g_outcnt[row] : g_incnt[row];
    cnt = min(cnt, CAP);
    ull acc = 0;
    int t = 0;
    for (; t + 8 <= cnt; t += 8) {
        int j[8];
        #pragma unroll
        for (int u = 0; u < 8; u++) j[u] = __ldg(cl + t + u);
        ull v[8];
        #pragma unroll
        for (int u = 0; u < 8; u++) v[u] = hb[(size_t)j[u] * 32 + lane];
        #pragma unroll
        for (int u = 0; u < 8; u++) add2(acc, v[u]);
    }
    for (; t < cnt; t++) add2(acc, hb[(size_t)cl[t] * 32 + lane]);
    float* dst = (dir ? g_aout : g_ain) + (size_t)row * Hh;
    *reinterpret_cast<ull*>(dst + 2 * lane) = acc;
}

// ------------------------- GRU via mma.sync tf32 (3xTF32) -------------------------
// Per CTA tile: 64 rows x 192 outs. Persistent grid (148), W resident in smem.
// smem floats: sW[192][196] | sWh2[64][68] | sX[64][196] | bias[192]
#define WP   196
#define W2P  68
#define OFF_W    0
#define OFF_WH2  (192*WP)                 // 37632
#define OFF_X    (OFF_WH2 + 64*W2P)       // 41984
#define OFF_B    (OFF_X + 64*WP)          // 54528
#define GRUM_FLOATS (OFF_B + 192)         // 54720
#define GRUM_SMEM (GRUM_FLOATS*4)         // 218880
#define NTILE (ROWS/64)                   // 512

__global__ void __launch_bounds__(256, 1)
gru_m(const float* __restrict__ Wz, const float* __restrict__ bz,
      const float* __restrict__ Wr, const float* __restrict__ br,
      const float* __restrict__ Wh, const float* __restrict__ bh) {
    extern __shared__ float sm[];
    float* sW   = sm + OFF_W;
    float* sWh2 = sm + OFF_WH2;
    float* sX   = sm + OFF_X;
    float* sB   = sm + OFF_B;

    int tid  = threadIdx.x;
    int w    = tid >> 5;
    int lane = tid & 31;
    int g    = lane >> 2;     // 0..7
    int t    = lane & 3;      // 0..3
    int half = w & 1;
    int r0   = (w >> 1) * 16;

    // ---- stage weights once ----
    for (int idx = tid; idx < 192 * 48; idx += 256) {
        int n = idx / 48, q = idx - n * 48;
        int k = q * 4;
        float4 v;
        if (n < 64)            v = *reinterpret_cast<const float4*>(Wz + n * 192 + k);
        else if (n < 128)      v = *reinterpret_cast<const float4*>(Wr + (n - 64) * 192 + k);
        else if (k < 128)      v = *reinterpret_cast<const float4*>(Wh + (n - 128) * 192 + k);
        else                   v = make_float4(0.f, 0.f, 0.f, 0.f);
        *reinterpret_cast<float4*>(sW + n * WP + k) = v;
    }
    for (int idx = tid; idx < 64 * 16; idx += 256) {
        int n = idx >> 4, q = idx & 15;
        *reinterpret_cast<float4*>(sWh2 + n * W2P + q * 4) =
            *reinterpret_cast<const float4*>(Wh + n * 192 + 128 + q * 4);
    }
    for (int i = tid; i < 192; i += 256)
        sB[i] = (i < 64) ? bz[i] : (i < 128) ? br[i - 64] : bh[i - 128];

    // n-tile bases for this warp (phase A)
    int nb[12];
    #pragma unroll
    for (int j = 0; j < 8; j++)  nb[j] = half * 64 + j * 8;
    #pragma unroll
    for (int j = 8; j < 12; j++) nb[j] = 128 + half * 32 + (j - 8) * 8;

    __syncthreads();

    for (int tile = blockIdx.x; tile < NTILE; tile += gridDim.x) {
        int tb = tile * 64;
        // ---- stage X tile: [64 rows][a_in|a_out|h] ----
        for (int idx = tid; idx < 64 * 48; idx += 256) {
            int row = idx / 48, q = idx - row * 48;
            int c = q * 4;
            const float* src = (c < 64) ? (g_ain + (size_t)(tb + row) * 64 + c)
                             : (c < 128) ? (g_aout + (size_t)(tb + row) * 64 + c - 64)
                                         : (g_h + (size_t)(tb + row) * 64 + c - 128);
            *reinterpret_cast<float4*>(sX + row * WP + c) =
                *reinterpret_cast<const float4*>(src);
        }
        __syncthreads();

        float acc[12][4];
        #pragma unroll
        for (int j = 0; j < 12; j++) {
            acc[j][0] = 0.f; acc[j][1] = 0.f; acc[j][2] = 0.f; acc[j][3] = 0.f;
        }

        // ---- phase A: k = 0..191 ----
        const float* xbase = sX + (r0 + g) * WP + t;
        #pragma unroll 2
        for (int ks = 0; ks < 24; ks++) {
            int k0 = ks * 8;
            uint32_t aH[4], aL[4];
            split2(xbase[k0],            aH[0], aL[0]);
            split2(xbase[8 * WP + k0],   aH[1], aL[1]);
            split2(xbase[k0 + 4],        aH[2], aL[2]);
            split2(xbase[8 * WP + k0+4], aH[3], aL[3]);
            #pragma unroll
            for (int j = 0; j < 12; j++) {
                const float* wp = sW + (nb[j] + g) * WP + k0 + t;
                uint32_t bh0, bl0, bh1, bl1;
                split2(wp[0], bh0, bl0);
                split2(wp[4], bh1, bl1);
                mma8(acc[j], aH[0], aH[1], aH[2], aH[3], bh0, bh1);
                mma8(acc[j], aL[0], aL[1], aL[2], aL[3], bh0, bh1);
                mma8(acc[j], aH[0], aH[1], aH[2], aH[3], bl0, bl1);
            }
        }
        __syncthreads();

        // ---- epilogue 1: z -> sX[.,64..127], rh -> sX[.,0..63] ----
        {
            int ra = r0 + g, rb = r0 + g + 8;
            if (half) {
                #pragma unroll
                for (int j = 0; j < 8; j++) {
                    int c0 = j * 8 + 2 * t;
                    float b0 = sB[64 + c0], b1 = sB[64 + c0 + 1];
                    sX[ra * WP + c0]     = sigmoidf_(acc[j][0] + b0) * sX[ra * WP + 128 + c0];
                    sX[ra * WP + c0 + 1] = sigmoidf_(acc[j][1] + b1) * sX[ra * WP + 128 + c0 + 1];
                    sX[rb * WP + c0]     = sigmoidf_(acc[j][2] + b0) * sX[rb * WP + 128 + c0];
                    sX[rb * WP + c0 + 1] = sigmoidf_(acc[j][3] + b1) * sX[rb * WP + 128 + c0 + 1];
                }
            } else {
                #pragma unroll
                for (int j = 0; j < 8; j++) {
                    int c0 = j * 8 + 2 * t;
                    float b0 = sB[c0], b1 = sB[c0 + 1];
                    sX[ra * WP + 64 + c0]     = sigmoidf_(acc[j][0] + b0);
                    sX[ra * WP + 64 + c0 + 1] = sigmoidf_(acc[j][1] + b1);
                    sX[rb * WP + 64 + c0]     = sigmoidf_(acc[j][2] + b0);
                    sX[rb * WP + 64 + c0 + 1] = sigmoidf_(acc[j][3] + b1);
                }
            }
        }
        __syncthreads();

        // ---- phase B: hn += rh @ Wh2^T, k = 0..63 ----
        #pragma unroll
        for (int ks = 0; ks < 8; ks++) {
            int k0 = ks * 8;
            uint32_t aH[4], aL[4];
            split2(xbase[k0],            aH[0], aL[0]);
            split2(xbase[8 * WP + k0],   aH[1], aL[1]);
            split2(xbase[k0 + 4],        aH[2], aL[2]);
            split2(xbase[8 * WP + k0+4], aH[3], aL[3]);
            #pragma unroll
            for (int j = 0; j < 4; j++) {
                int n2 = half * 32 + j * 8;
                const float* wp = sWh2 + (n2 + g) * W2P + k0 + t;
                uint32_t bh0, bl0, bh1, bl1;
                split2(wp[0], bh0, bl0);
                split2(wp[4], bh1, bl1);
                mma8(acc[8 + j], aH[0], aH[1], aH[2], aH[3], bh0, bh1);
                mma8(acc[8 + j], aL[0], aL[1], aL[2], aL[3], bh0, bh1);
                mma8(acc[8 + j], aH[0], aH[1], aH[2], aH[3], bl0, bl1);
            }
        }
        __syncthreads();

        // ---- hn -> sX[.,0..63] ----
        {
            int ra = r0 + g, rb = r0 + g + 8;
            #pragma unroll
            for (int j = 0; j < 4; j++) {
                int c0 = half * 32 + j * 8 + 2 * t;
                float b0 = sB[128 + c0], b1 = sB[128 + c0 + 1];
                sX[ra * WP + c0]     = tanhf_(acc[8 + j][0] + b0);
                sX[ra * WP + c0 + 1] = tanhf_(acc[8 + j][1] + b1);
                sX[rb * WP + c0]     = tanhf_(acc[8 + j][2] + b0);
                sX[rb * WP + c0 + 1] = tanhf_(acc[8 + j][3] + b1);
            }
        }
        __syncthreads();

        // ---- final update: h' = h + z*(hn - h) ----
        {
            int row = tid >> 2;
            int cb  = (tid & 3) * 16;
            #pragma unroll
            for (int u = 0; u < 4; u++) {
                int cc = cb + u * 4;
                float4 hn4 = *reinterpret_cast<float4*>(sX + row * WP + cc);
                float4 z4  = *reinterpret_cast<float4*>(sX + row * WP + 64 + cc);
                float4 h4  = *reinterpret_cast<float4*>(sX + row * WP + 128 + cc);
                float4 o;
                o.x = h4.x + z4.x * (hn4.x - h4.x);
                o.y = h4.y + z4.y * (hn4.y - h4.y);
                o.z = h4.z + z4.z * (hn4.z - h4.z);
                o.w = h4.w + z4.w * (hn4.w - h4.w);
                *reinterpret_cast<float4*>(g_h + (size_t)(tb + row) * 64 + cc) = o;
            }
        }
        __syncthreads();   // sX reuse next tile
    }
}

// out[row] = dot(h[row], Wo) + bo
__global__ void out_k(const float* __restrict__ Wo, const float* __restrict__ bo,
                      float* __restrict__ out) {
    int row  = blockIdx.x * 8 + (threadIdx.x >> 5);
    int lane = threadIdx.x & 31;
    const float* hr = g_h + (size_t)row * Hh;
    float a = hr[lane] * Wo[lane] + hr[lane + 32] * Wo[lane + 32];
    #pragma unroll
    for (int o = 16; o; o >>= 1) a += __shfl_xor_sync(0xffffffffu, a, o);
    if (lane == 0) out[row] = a + bo[0];
}

// ------------------------- launch -------------------------
extern "C" void kernel_launch(void* const* d_in, const int* in_sizes, int n_in,
                              void* d_out, int out_size) {
    const float* attr = (const float*)d_in[0];
    const float* adj  = (const float*)d_in[1];
    const float* Wi   = (const float*)d_in[2];
    const float* bi   = (const float*)d_in[3];
    const float* Wz   = (const float*)d_in[4];
    const float* bz   = (const float*)d_in[5];
    const float* Wr   = (const float*)d_in[6];
    const float* br   = (const float*)d_in[7];
    const float* Wh   = (const float*)d_in[8];
    const float* bh   = (const float*)d_in[9];
    const float* Wo   = (const float*)d_in[10];
    const float* bo   = (const float*)d_in[11];
    float* out = (float*)d_out;

    static bool attr_set = false;
    if (!attr_set) {
        cudaFuncSetAttribute(gru_m, cudaFuncAttributeMaxDynamicSharedMemorySize, GRUM_SMEM);
        attr_set = true;
    }

    zero_counts<<<(ROWS + 255) / 256, 256>>>();
    build_csr<<<ROWS, 256>>>(adj);
    init_h<<<ROWS / 4, 256>>>(attr, Wi, bi);
    probe<<<1, 32>>>();   // aligns ncu -s 5 onto gru_m
    for (int s = 0; s < STEPS; s++) {
        spmm2<<<ROWS / 4, 256>>>();
        gru_m<<<148, 256, GRUM_SMEM>>>(Wz, bz, Wr, br, Wh, bh);
    }
    out_k<<<ROWS / 8, 256>>>(Wo, bo, out);
}